// round 1
// baseline (speedup 1.0000x reference)
#include <cuda_runtime.h>
#include <math.h>

// Problem dims
#define BB 2
#define NN 2048
#define DD 1024
#define HH 16
#define EE 64
#define FF 4096
#define BN (BB*NN)   // 4096

// Scratch (device globals: no allocation allowed)
__device__ float g_h [BN*DD];   // LN1 output, later reused as attention output
__device__ float g_q [BN*DD];
__device__ float g_k [BN*DD];
__device__ float g_v [BN*DD];
__device__ float g_h2[BN*DD];
__device__ float g_m [(size_t)BN*FF];

// ---------------------------------------------------------------------------
// Block-wide 2-value sum reduction (256 threads)
// ---------------------------------------------------------------------------
__device__ __forceinline__ void block_reduce2(float& a, float& b) {
  #pragma unroll
  for (int o = 16; o > 0; o >>= 1) {
    a += __shfl_xor_sync(0xffffffffu, a, o);
    b += __shfl_xor_sync(0xffffffffu, b, o);
  }
  __shared__ float sa[8], sb[8];
  int w = threadIdx.x >> 5, l = threadIdx.x & 31;
  if (l == 0) { sa[w] = a; sb[w] = b; }
  __syncthreads();
  float ra = (l < 8) ? sa[l] : 0.f;
  float rb = (l < 8) ? sb[l] : 0.f;
  #pragma unroll
  for (int o = 4; o > 0; o >>= 1) {
    ra += __shfl_xor_sync(0xffffffffu, ra, o);
    rb += __shfl_xor_sync(0xffffffffu, rb, o);
  }
  if (threadIdx.x == 0) { sa[0] = ra; sb[0] = rb; }
  __syncthreads();
  a = sa[0]; b = sb[0];
}

// ---------------------------------------------------------------------------
// LayerNorm kernel: dst[r] = LN(src[r] (+ add[r]))*g + b, optional ReLU.
// One block of 256 threads per row. Row cached in smem.
// ---------------------------------------------------------------------------
template<int COLS, bool RELU, bool ADD>
__global__ void ln_kernel(const float* __restrict__ src,
                          const float* __restrict__ addsrc,
                          const float* __restrict__ gw,
                          const float* __restrict__ bw,
                          float* __restrict__ dst)
{
  __shared__ float row[COLS];
  const size_t r = blockIdx.x;
  const float4* s4 = (const float4*)(src + r * COLS);
  const float4* a4 = ADD ? (const float4*)(addsrc + r * COLS) : nullptr;

  float sum = 0.f, sq = 0.f;
  #pragma unroll
  for (int i = threadIdx.x; i < COLS/4; i += 256) {
    float4 v = s4[i];
    if (ADD) {
      float4 a = a4[i];
      v.x += a.x; v.y += a.y; v.z += a.z; v.w += a.w;
    }
    ((float4*)row)[i] = v;
    sum += v.x + v.y + v.z + v.w;
    sq  += v.x*v.x + v.y*v.y + v.z*v.z + v.w*v.w;
  }
  block_reduce2(sum, sq);
  const float mu  = sum * (1.0f / COLS);
  const float var = sq * (1.0f / COLS) - mu * mu;
  const float inv = rsqrtf(var + 1e-5f);

  #pragma unroll
  for (int i = threadIdx.x; i < COLS/4; i += 256) {
    float4 v = ((float4*)row)[i];
    float4 g = ((const float4*)gw)[i];
    float4 b = ((const float4*)bw)[i];
    float4 o;
    o.x = (v.x - mu) * inv * g.x + b.x;
    o.y = (v.y - mu) * inv * g.y + b.y;
    o.z = (v.z - mu) * inv * g.z + b.z;
    o.w = (v.w - mu) * inv * g.w + b.w;
    if (RELU) {
      o.x = fmaxf(o.x, 0.f); o.y = fmaxf(o.y, 0.f);
      o.z = fmaxf(o.z, 0.f); o.w = fmaxf(o.w, 0.f);
    }
    ((float4*)(dst + r * COLS))[i] = o;
  }
}

// ---------------------------------------------------------------------------
// SGEMM (NT): C[M,Ncols] = A[M,K] @ W[Ncols,K]^T + bias
// Both A and W are K-contiguous row-major (PyTorch-style weight layout).
// 128x128 block tile, K-tile 16, 256 threads, 8x8 per-thread micro-tile.
// Requires M%128==0, Ncols%128==0, K%16==0 (true for all uses here).
// ---------------------------------------------------------------------------
__global__ void __launch_bounds__(256, 2) sgemm_nt(
    const float* __restrict__ A, const float* __restrict__ W,
    const float* __restrict__ bias, float* __restrict__ C,
    int M, int Ncols, int K)
{
  __shared__ float As[16][128];
  __shared__ float Bs[16][128];
  const int bm = blockIdx.y * 128;
  const int bn = blockIdx.x * 128;
  const int tid = threadIdx.x;
  const int tx = tid & 15;        // col group 0..15
  const int ty = tid >> 4;        // row group 0..15
  const int lr = tid >> 2;        // load row 0..63
  const int lk = (tid & 3) << 2;  // load k 0,4,8,12

  const float* Ap = A + (size_t)(bm + lr) * K + lk;
  const float* Wp = W + (size_t)(bn + lr) * K + lk;

  float acc[8][8];
  #pragma unroll
  for (int i = 0; i < 8; i++)
    #pragma unroll
    for (int j = 0; j < 8; j++) acc[i][j] = 0.f;

  for (int k0 = 0; k0 < K; k0 += 16) {
    float4 a0 = *(const float4*)(Ap + k0);
    float4 a1 = *(const float4*)(Ap + (size_t)64 * K + k0);
    float4 b0 = *(const float4*)(Wp + k0);
    float4 b1 = *(const float4*)(Wp + (size_t)64 * K + k0);
    __syncthreads();
    As[lk+0][lr] = a0.x; As[lk+1][lr] = a0.y; As[lk+2][lr] = a0.z; As[lk+3][lr] = a0.w;
    As[lk+0][lr+64] = a1.x; As[lk+1][lr+64] = a1.y; As[lk+2][lr+64] = a1.z; As[lk+3][lr+64] = a1.w;
    Bs[lk+0][lr] = b0.x; Bs[lk+1][lr] = b0.y; Bs[lk+2][lr] = b0.z; Bs[lk+3][lr] = b0.w;
    Bs[lk+0][lr+64] = b1.x; Bs[lk+1][lr+64] = b1.y; Bs[lk+2][lr+64] = b1.z; Bs[lk+3][lr+64] = b1.w;
    __syncthreads();
    #pragma unroll
    for (int kk = 0; kk < 16; kk++) {
      float4 ra0 = *(const float4*)&As[kk][ty*8];
      float4 ra1 = *(const float4*)&As[kk][ty*8 + 4];
      float4 rb0 = *(const float4*)&Bs[kk][tx*8];
      float4 rb1 = *(const float4*)&Bs[kk][tx*8 + 4];
      float ra[8] = {ra0.x, ra0.y, ra0.z, ra0.w, ra1.x, ra1.y, ra1.z, ra1.w};
      float rb[8] = {rb0.x, rb0.y, rb0.z, rb0.w, rb1.x, rb1.y, rb1.z, rb1.w};
      #pragma unroll
      for (int i = 0; i < 8; i++)
        #pragma unroll
        for (int j = 0; j < 8; j++)
          acc[i][j] = fmaf(ra[i], rb[j], acc[i][j]);
    }
  }

  #pragma unroll
  for (int i = 0; i < 8; i++) {
    float* cp = C + (size_t)(bm + ty*8 + i) * Ncols + bn + tx*8;
    #pragma unroll
    for (int j = 0; j < 8; j += 4) {
      float4 o;
      o.x = acc[i][j+0] + bias[bn + tx*8 + j+0];
      o.y = acc[i][j+1] + bias[bn + tx*8 + j+1];
      o.z = acc[i][j+2] + bias[bn + tx*8 + j+2];
      o.w = acc[i][j+3] + bias[bn + tx*8 + j+3];
      *(float4*)(cp + j) = o;
    }
  }
}

// ---------------------------------------------------------------------------
// Causal flash attention, fp32. Q/K/V in [BN, D] layout (head h at cols h*64..).
// Grid: (N/64 query tiles, B*H). Block: 64 threads, 1 thread = 1 query row.
// Online softmax; scale = sqrt(D) = 32 (faithful to reference).
// ---------------------------------------------------------------------------
__global__ void __launch_bounds__(64) attn_kernel(
    const float* __restrict__ Q, const float* __restrict__ Kx,
    const float* __restrict__ V, float* __restrict__ O)
{
  __shared__ float Ks[64][64];
  __shared__ float Vs[64][64];

  const int bh = blockIdx.y;
  const int b  = bh / HH;
  const int h  = bh % HH;
  const int tid = threadIdx.x;
  const int n  = blockIdx.x * 64 + tid;          // query position
  const size_t base = (size_t)b * NN * DD + (size_t)h * EE;

  // Load this thread's query row into registers
  float q[64];
  {
    const float4* qp = (const float4*)(Q + base + (size_t)n * DD);
    #pragma unroll
    for (int i = 0; i < 16; i++) {
      float4 t = qp[i];
      q[4*i+0] = t.x; q[4*i+1] = t.y; q[4*i+2] = t.z; q[4*i+3] = t.w;
    }
  }

  float acc[64];
  #pragma unroll
  for (int e = 0; e < 64; e++) acc[e] = 0.f;
  float mx = -3.0e38f, l = 0.f;

  const float* kp = Kx + base;
  const float* vp = V + base;

  for (int kt = 0; kt <= blockIdx.x; kt++) {
    __syncthreads();
    // Cooperative coalesced tile load: 64x64 floats each for K and V
    #pragma unroll
    for (int i = 0; i < 16; i++) {
      int idx = tid + (i << 6);
      int r = idx >> 4, c = idx & 15;
      ((float4*)Ks[r])[c] = ((const float4*)(kp + (size_t)(kt*64 + r) * DD))[c];
      ((float4*)Vs[r])[c] = ((const float4*)(vp + (size_t)(kt*64 + r) * DD))[c];
    }
    __syncthreads();

    const int jmax = (kt == blockIdx.x) ? tid : 63;   // causal bound (inclusive)
    for (int j = 0; j <= jmax; j++) {
      float s = 0.f;
      const float4* kr = (const float4*)Ks[j];
      #pragma unroll
      for (int i = 0; i < 16; i++) {
        float4 kv = kr[i];
        s = fmaf(q[4*i+0], kv.x, s);
        s = fmaf(q[4*i+1], kv.y, s);
        s = fmaf(q[4*i+2], kv.z, s);
        s = fmaf(q[4*i+3], kv.w, s);
      }
      s *= 32.0f;                                    // sqrt(D)
      if (s > mx) {
        float f = __expf(mx - s);                    // 0 on first hit
        l *= f;
        #pragma unroll
        for (int e = 0; e < 64; e++) acc[e] *= f;
        mx = s;
      }
      float p = __expf(s - mx);
      l += p;
      const float4* vr = (const float4*)Vs[j];
      #pragma unroll
      for (int i = 0; i < 16; i++) {
        float4 vv = vr[i];
        acc[4*i+0] = fmaf(p, vv.x, acc[4*i+0]);
        acc[4*i+1] = fmaf(p, vv.y, acc[4*i+1]);
        acc[4*i+2] = fmaf(p, vv.z, acc[4*i+2]);
        acc[4*i+3] = fmaf(p, vv.w, acc[4*i+3]);
      }
    }
  }

  const float inv = 1.0f / l;
  float4* op = (float4*)(O + base + (size_t)n * DD);
  #pragma unroll
  for (int i = 0; i < 16; i++) {
    float4 o;
    o.x = acc[4*i+0] * inv; o.y = acc[4*i+1] * inv;
    o.z = acc[4*i+2] * inv; o.w = acc[4*i+3] * inv;
    op[i] = o;
  }
}

// ---------------------------------------------------------------------------
// Launch
// ---------------------------------------------------------------------------
extern "C" void kernel_launch(void* const* d_in, const int* in_sizes, int n_in,
                              void* d_out, int out_size)
{
  const float* x        = (const float*)d_in[0];
  const float* wq       = (const float*)d_in[1];
  const float* bq       = (const float*)d_in[2];
  const float* wk       = (const float*)d_in[3];
  const float* bk       = (const float*)d_in[4];
  const float* wv       = (const float*)d_in[5];
  const float* bv       = (const float*)d_in[6];
  const float* w1       = (const float*)d_in[7];
  const float* b1       = (const float*)d_in[8];
  const float* ln_mlp_g = (const float*)d_in[9];
  const float* ln_mlp_b = (const float*)d_in[10];
  const float* w2       = (const float*)d_in[11];
  const float* b2       = (const float*)d_in[12];
  const float* ln1_g    = (const float*)d_in[13];
  const float* ln1_b    = (const float*)d_in[14];
  const float* ln2_g    = (const float*)d_in[15];
  const float* ln2_b    = (const float*)d_in[16];
  float* out = (float*)d_out;

  void* p;
  cudaGetSymbolAddress(&p, g_h);  float* h  = (float*)p;
  cudaGetSymbolAddress(&p, g_q);  float* q  = (float*)p;
  cudaGetSymbolAddress(&p, g_k);  float* k  = (float*)p;
  cudaGetSymbolAddress(&p, g_v);  float* v  = (float*)p;
  cudaGetSymbolAddress(&p, g_h2); float* h2 = (float*)p;
  cudaGetSymbolAddress(&p, g_m);  float* m  = (float*)p;

  // 1. h = LN1(x)
  ln_kernel<DD, false, false><<<BN, 256>>>(x, nullptr, ln1_g, ln1_b, h);

  // 2. QKV projections (kept in [BN, D]; head h occupies cols h*64..h*64+63)
  sgemm_nt<<<dim3(DD/128, BN/128), 256>>>(h, wq, bq, q, BN, DD, DD);
  sgemm_nt<<<dim3(DD/128, BN/128), 256>>>(h, wk, bk, k, BN, DD, DD);
  sgemm_nt<<<dim3(DD/128, BN/128), 256>>>(h, wv, bv, v, BN, DD, DD);

  // 3. Causal attention -> reuse g_h as attention output
  attn_kernel<<<dim3(NN/64, BB*HH), 64>>>(q, k, v, h);

  // 4. h2 = LN2(x + attn)
  ln_kernel<DD, false, true><<<BN, 256>>>(x, h, ln2_g, ln2_b, h2);

  // 5. m = h2 @ w1^T + b1 ; then m = relu(LN_mlp(m)) in place
  sgemm_nt<<<dim3(FF/128, BN/128), 256>>>(h2, w1, b1, m, BN, FF, DD);
  ln_kernel<FF, true, false><<<BN, 256>>>(m, nullptr, ln_mlp_g, ln_mlp_b, m);

  // 6. out = m @ w2^T + b2
  sgemm_nt<<<dim3(DD/128, BN/128), 256>>>(m, w2, b2, out, BN, DD, FF);
}

// round 3
// speedup vs baseline: 1.7359x; 1.7359x over previous
#include <cuda_runtime.h>
#include <cuda_bf16.h>
#include <math.h>
#include <stdint.h>

// Problem dims
#define BB 2
#define NN 2048
#define DD 1024
#define HH 16
#define EE 64
#define FF 4096
#define BN (BB*NN)   // 4096

// ---------------------------------------------------------------------------
// Scratch (device globals: no allocation allowed)
// ---------------------------------------------------------------------------
__device__ float g_h [BN*DD];
__device__ float g_q [BN*DD];
__device__ float g_k [BN*DD];
__device__ float g_v [BN*DD];
__device__ float g_h2[BN*DD];
__device__ float g_m [(size_t)BN*FF];
__device__ __nv_bfloat16 g_ah[(size_t)BN*FF];   // activation hi split
__device__ __nv_bfloat16 g_al[(size_t)BN*FF];   // activation lo split
__device__ __nv_bfloat16 g_wh[(size_t)FF*DD];   // weight hi split
__device__ __nv_bfloat16 g_wl[(size_t)FF*DD];   // weight lo split

// ---------------------------------------------------------------------------
// Helpers
// ---------------------------------------------------------------------------
__device__ __forceinline__ uint32_t s2u(const void* p) {
  uint32_t a;
  asm("{ .reg .u64 t; cvta.to.shared.u64 t, %1; cvt.u32.u64 %0, t; }" : "=r"(a) : "l"(p));
  return a;
}

#define SWZ(off) ((off) ^ (((off) >> 3) & 0x70))

__device__ __forceinline__ void cp16(uint32_t dst, const void* src) {
  asm volatile("cp.async.cg.shared.global [%0], [%1], 16;"
               :: "r"(dst), "l"(__cvta_generic_to_global(src)) : "memory");
}
__device__ __forceinline__ void cp_commit() {
  asm volatile("cp.async.commit_group;" ::: "memory");
}
template<int N>
__device__ __forceinline__ void cp_wait() {
  asm volatile("cp.async.wait_group %0;" :: "n"(N) : "memory");
}

__device__ __forceinline__ void ldsm4(uint32_t* r, uint32_t addr) {
  asm volatile("ldmatrix.sync.aligned.m8n8.x4.shared.b16 {%0,%1,%2,%3}, [%4];"
               : "=r"(r[0]), "=r"(r[1]), "=r"(r[2]), "=r"(r[3]) : "r"(addr));
}

__device__ __forceinline__ void mma16816(float* c, const uint32_t* a, uint32_t b0, uint32_t b1) {
  asm volatile(
    "mma.sync.aligned.m16n8k16.row.col.f32.bf16.bf16.f32 "
    "{%0,%1,%2,%3}, {%4,%5,%6,%7}, {%8,%9}, {%0,%1,%2,%3};"
    : "+f"(c[0]), "+f"(c[1]), "+f"(c[2]), "+f"(c[3])
    : "r"(a[0]), "r"(a[1]), "r"(a[2]), "r"(a[3]), "r"(b0), "r"(b1));
}

// ---------------------------------------------------------------------------
// fp32 -> bf16 hi/lo split (elementwise)
// ---------------------------------------------------------------------------
__global__ void split_kernel(const float* __restrict__ src,
                             __nv_bfloat16* __restrict__ hi,
                             __nv_bfloat16* __restrict__ lo, int n4) {
  int i = blockIdx.x * blockDim.x + threadIdx.x;
  if (i >= n4) return;
  float4 v = ((const float4*)src)[i];
  __nv_bfloat16 hx = __float2bfloat16(v.x);
  __nv_bfloat16 hy = __float2bfloat16(v.y);
  __nv_bfloat16 hz = __float2bfloat16(v.z);
  __nv_bfloat16 hw = __float2bfloat16(v.w);
  __nv_bfloat162* h2 = (__nv_bfloat162*)hi;
  __nv_bfloat162* l2 = (__nv_bfloat162*)lo;
  h2[2*i+0] = __nv_bfloat162(hx, hy);
  h2[2*i+1] = __nv_bfloat162(hz, hw);
  __nv_bfloat16 lx = __float2bfloat16(v.x - __bfloat162float(hx));
  __nv_bfloat16 ly = __float2bfloat16(v.y - __bfloat162float(hy));
  __nv_bfloat16 lz = __float2bfloat16(v.z - __bfloat162float(hz));
  __nv_bfloat16 lw = __float2bfloat16(v.w - __bfloat162float(hw));
  l2[2*i+0] = __nv_bfloat162(lx, ly);
  l2[2*i+1] = __nv_bfloat162(lz, lw);
}

// ---------------------------------------------------------------------------
// bf16x3 warp-MMA GEMM: C[M,Ncols] = (Ah+Al)[M,K] @ (Wh+Wl)[Ncols,K]^T + bias
// Block tile 128x128, BK=64, double-buffered cp.async, SW128 smem swizzle.
// 256 threads = 8 warps (4x2), warp tile 32x64, mma.sync m16n8k16 bf16.
// ---------------------------------------------------------------------------
#define STAGE_BYTES 65536          // 4 operands x 16KB
#define OPB 16384
#define GEMM_SMEM (2 * STAGE_BYTES)

__global__ void __launch_bounds__(256) gemm_mma(
    const __nv_bfloat16* __restrict__ Ah, const __nv_bfloat16* __restrict__ Al,
    const __nv_bfloat16* __restrict__ Wh, const __nv_bfloat16* __restrict__ Wl,
    const float* __restrict__ bias, float* __restrict__ C,
    int M, int Ncols, int K)
{
  extern __shared__ char smem[];
  const uint32_t smem_u = s2u(smem);
  const int tid  = threadIdx.x;
  const int wid  = tid >> 5;
  const int lane = tid & 31;
  const int warp_m = wid & 3;         // 0..3  (M direction, 32 rows each)
  const int warp_n = wid >> 2;        // 0..1  (N direction, 64 cols each)
  const int bm = blockIdx.y * 128;
  const int bn = blockIdx.x * 128;
  const int T = K >> 6;

  const __nv_bfloat16* srcs[4];
  srcs[0] = Ah + (size_t)bm * K;
  srcs[1] = Al + (size_t)bm * K;
  srcs[2] = Wh + (size_t)bn * K;
  srcs[3] = Wl + (size_t)bn * K;

  // per-thread load coords (4 chunks of 16B per operand per stage)
  int lrow[4], lcol[4];
  #pragma unroll
  for (int i = 0; i < 4; i++) {
    int chunk = i * 256 + tid;        // 0..1023
    lrow[i] = chunk >> 3;             // 0..127
    lcol[i] = chunk & 7;              // 0..7 (16B units)
  }

  auto load_stage = [&](int t) {
    const uint32_t sb = smem_u + (uint32_t)(t & 1) * STAGE_BYTES;
    const int k0 = t << 6;
    #pragma unroll
    for (int op = 0; op < 4; op++) {
      const __nv_bfloat16* s = srcs[op] + k0;
      #pragma unroll
      for (int i = 0; i < 4; i++) {
        const uint32_t dst = sb + op * OPB + SWZ(lrow[i] * 128 + lcol[i] * 16);
        cp16(dst, s + (size_t)lrow[i] * K + lcol[i] * 8);
      }
    }
    cp_commit();
  };

  float acc[2][8][4];
  #pragma unroll
  for (int mt = 0; mt < 2; mt++)
    #pragma unroll
    for (int nt = 0; nt < 8; nt++)
      #pragma unroll
      for (int j = 0; j < 4; j++) acc[mt][nt][j] = 0.f;

  load_stage(0);

  const int arow = warp_m * 32 + (lane & 15);
  const int brow = warp_n * 64 + (lane & 15);
  const int kchunk = (lane >> 4) * 16;   // +8 k elems for upper half

  for (int t = 0; t < T; t++) {
    if (t + 1 < T) { load_stage(t + 1); cp_wait<1>(); }
    else          { cp_wait<0>(); }
    __syncthreads();

    const uint32_t sb  = smem_u + (uint32_t)(t & 1) * STAGE_BYTES;
    const uint32_t sAh = sb, sAl = sb + OPB, sWh = sb + 2*OPB, sWl = sb + 3*OPB;

    #pragma unroll
    for (int ks = 0; ks < 4; ks++) {
      const int koff = ks * 32 + kchunk;
      uint32_t ah[2][4], al[2][4], wh[4][4], wl[4][4];
      #pragma unroll
      for (int mt = 0; mt < 2; mt++) {
        const uint32_t off = SWZ((arow + mt*16) * 128 + koff);
        ldsm4(ah[mt], sAh + off);
        ldsm4(al[mt], sAl + off);
      }
      #pragma unroll
      for (int ng = 0; ng < 4; ng++) {
        const uint32_t off = SWZ((brow + ng*16) * 128 + koff);
        ldsm4(wh[ng], sWh + off);
        ldsm4(wl[ng], sWl + off);
      }
      #pragma unroll
      for (int mt = 0; mt < 2; mt++) {
        #pragma unroll
        for (int nt = 0; nt < 8; nt++) {
          const int ng = nt >> 1, half = nt & 1;
          mma16816(acc[mt][nt], ah[mt], wh[ng][half], wh[ng][half+2]);
          mma16816(acc[mt][nt], ah[mt], wl[ng][half], wl[ng][half+2]);
          mma16816(acc[mt][nt], al[mt], wh[ng][half], wh[ng][half+2]);
        }
      }
    }
    __syncthreads();
  }

  // Epilogue: D[g][2tg], D[g][2tg+1], D[g+8][2tg], D[g+8][2tg+1] per tile
  const int g  = lane >> 2;
  const int tg = lane & 3;
  #pragma unroll
  for (int mt = 0; mt < 2; mt++) {
    const int r0 = bm + warp_m*32 + mt*16 + g;
    #pragma unroll
    for (int nt = 0; nt < 8; nt++) {
      const int col = bn + warp_n*64 + nt*8 + tg*2;
      const float b0 = bias[col], b1 = bias[col+1];
      float2* p0 = (float2*)(C + (size_t)r0 * Ncols + col);
      float2* p1 = (float2*)(C + (size_t)(r0+8) * Ncols + col);
      *p0 = make_float2(acc[mt][nt][0] + b0, acc[mt][nt][1] + b1);
      *p1 = make_float2(acc[mt][nt][2] + b0, acc[mt][nt][3] + b1);
    }
  }
}

// ---------------------------------------------------------------------------
// Block-wide 2-value sum reduction (256 threads)
// ---------------------------------------------------------------------------
__device__ __forceinline__ void block_reduce2(float& a, float& b) {
  #pragma unroll
  for (int o = 16; o > 0; o >>= 1) {
    a += __shfl_xor_sync(0xffffffffu, a, o);
    b += __shfl_xor_sync(0xffffffffu, b, o);
  }
  __shared__ float sa[8], sb[8];
  int w = threadIdx.x >> 5, l = threadIdx.x & 31;
  if (l == 0) { sa[w] = a; sb[w] = b; }
  __syncthreads();
  float ra = (l < 8) ? sa[l] : 0.f;
  float rb = (l < 8) ? sb[l] : 0.f;
  #pragma unroll
  for (int o = 4; o > 0; o >>= 1) {
    ra += __shfl_xor_sync(0xffffffffu, ra, o);
    rb += __shfl_xor_sync(0xffffffffu, rb, o);
  }
  if (threadIdx.x == 0) { sa[0] = ra; sb[0] = rb; }
  __syncthreads();
  a = sa[0]; b = sb[0];
}

// ---------------------------------------------------------------------------
// LayerNorm kernel
// ---------------------------------------------------------------------------
template<int COLS, bool RELU, bool ADD>
__global__ void ln_kernel(const float* __restrict__ src,
                          const float* __restrict__ addsrc,
                          const float* __restrict__ gw,
                          const float* __restrict__ bw,
                          float* __restrict__ dst)
{
  __shared__ float row[COLS];
  const size_t r = blockIdx.x;
  const float4* s4 = (const float4*)(src + r * COLS);
  const float4* a4 = ADD ? (const float4*)(addsrc + r * COLS) : nullptr;

  float sum = 0.f, sq = 0.f;
  #pragma unroll
  for (int i = threadIdx.x; i < COLS/4; i += 256) {
    float4 v = s4[i];
    if (ADD) {
      float4 a = a4[i];
      v.x += a.x; v.y += a.y; v.z += a.z; v.w += a.w;
    }
    ((float4*)row)[i] = v;
    sum += v.x + v.y + v.z + v.w;
    sq  += v.x*v.x + v.y*v.y + v.z*v.z + v.w*v.w;
  }
  block_reduce2(sum, sq);
  const float mu  = sum * (1.0f / COLS);
  const float var = sq * (1.0f / COLS) - mu * mu;
  const float inv = rsqrtf(var + 1e-5f);

  #pragma unroll
  for (int i = threadIdx.x; i < COLS/4; i += 256) {
    float4 v = ((float4*)row)[i];
    float4 g = ((const float4*)gw)[i];
    float4 b = ((const float4*)bw)[i];
    float4 o;
    o.x = (v.x - mu) * inv * g.x + b.x;
    o.y = (v.y - mu) * inv * g.y + b.y;
    o.z = (v.z - mu) * inv * g.z + b.z;
    o.w = (v.w - mu) * inv * g.w + b.w;
    if (RELU) {
      o.x = fmaxf(o.x, 0.f); o.y = fmaxf(o.y, 0.f);
      o.z = fmaxf(o.z, 0.f); o.w = fmaxf(o.w, 0.f);
    }
    ((float4*)(dst + r * COLS))[i] = o;
  }
}

// ---------------------------------------------------------------------------
// Causal flash attention, fp32. 1 thread = 1 query row.
// ---------------------------------------------------------------------------
__global__ void __launch_bounds__(64) attn_kernel(
    const float* __restrict__ Q, const float* __restrict__ Kx,
    const float* __restrict__ V, float* __restrict__ O)
{
  __shared__ float Ks[64][64];
  __shared__ float Vs[64][64];

  const int bh = blockIdx.y;
  const int b  = bh / HH;
  const int h  = bh % HH;
  const int tid = threadIdx.x;
  const int n  = blockIdx.x * 64 + tid;
  const size_t base = (size_t)b * NN * DD + (size_t)h * EE;

  float q[64];
  {
    const float4* qp = (const float4*)(Q + base + (size_t)n * DD);
    #pragma unroll
    for (int i = 0; i < 16; i++) {
      float4 t = qp[i];
      q[4*i+0] = t.x; q[4*i+1] = t.y; q[4*i+2] = t.z; q[4*i+3] = t.w;
    }
  }

  float acc[64];
  #pragma unroll
  for (int e = 0; e < 64; e++) acc[e] = 0.f;
  float mx = -3.0e38f, l = 0.f;

  const float* kp = Kx + base;
  const float* vp = V + base;

  for (int kt = 0; kt <= blockIdx.x; kt++) {
    __syncthreads();
    #pragma unroll
    for (int i = 0; i < 16; i++) {
      int idx = tid + (i << 6);
      int r = idx >> 4, c = idx & 15;
      ((float4*)Ks[r])[c] = ((const float4*)(kp + (size_t)(kt*64 + r) * DD))[c];
      ((float4*)Vs[r])[c] = ((const float4*)(vp + (size_t)(kt*64 + r) * DD))[c];
    }
    __syncthreads();

    const int jmax = (kt == blockIdx.x) ? tid : 63;
    for (int j = 0; j <= jmax; j++) {
      float s = 0.f;
      const float4* kr = (const float4*)Ks[j];
      #pragma unroll
      for (int i = 0; i < 16; i++) {
        float4 kv = kr[i];
        s = fmaf(q[4*i+0], kv.x, s);
        s = fmaf(q[4*i+1], kv.y, s);
        s = fmaf(q[4*i+2], kv.z, s);
        s = fmaf(q[4*i+3], kv.w, s);
      }
      s *= 32.0f;
      if (s > mx) {
        float f = __expf(mx - s);
        l *= f;
        #pragma unroll
        for (int e = 0; e < 64; e++) acc[e] *= f;
        mx = s;
      }
      float p = __expf(s - mx);
      l += p;
      const float4* vr = (const float4*)Vs[j];
      #pragma unroll
      for (int i = 0; i < 16; i++) {
        float4 vv = vr[i];
        acc[4*i+0] = fmaf(p, vv.x, acc[4*i+0]);
        acc[4*i+1] = fmaf(p, vv.y, acc[4*i+1]);
        acc[4*i+2] = fmaf(p, vv.z, acc[4*i+2]);
        acc[4*i+3] = fmaf(p, vv.w, acc[4*i+3]);
      }
    }
  }

  const float inv = 1.0f / l;
  float4* op = (float4*)(O + base + (size_t)n * DD);
  #pragma unroll
  for (int i = 0; i < 16; i++) {
    float4 o;
    o.x = acc[4*i+0] * inv; o.y = acc[4*i+1] * inv;
    o.z = acc[4*i+2] * inv; o.w = acc[4*i+3] * inv;
    op[i] = o;
  }
}

// ---------------------------------------------------------------------------
// Launch
// ---------------------------------------------------------------------------
static void run_split(const float* src, __nv_bfloat16* hi, __nv_bfloat16* lo, int n) {
  int n4 = n / 4;
  split_kernel<<<(n4 + 255) / 256, 256>>>(src, hi, lo, n4);
}

static void run_gemm(const __nv_bfloat16* ah, const __nv_bfloat16* al,
                     const __nv_bfloat16* wh, const __nv_bfloat16* wl,
                     const float* bias, float* c, int M, int Ncols, int K) {
  cudaFuncSetAttribute(gemm_mma, cudaFuncAttributeMaxDynamicSharedMemorySize, GEMM_SMEM);
  gemm_mma<<<dim3(Ncols/128, M/128), 256, GEMM_SMEM>>>(ah, al, wh, wl, bias, c, M, Ncols, K);
}

extern "C" void kernel_launch(void* const* d_in, const int* in_sizes, int n_in,
                              void* d_out, int out_size)
{
  const float* x        = (const float*)d_in[0];
  const float* wq       = (const float*)d_in[1];
  const float* bq       = (const float*)d_in[2];
  const float* wk       = (const float*)d_in[3];
  const float* bk       = (const float*)d_in[4];
  const float* wv       = (const float*)d_in[5];
  const float* bv       = (const float*)d_in[6];
  const float* w1       = (const float*)d_in[7];
  const float* b1       = (const float*)d_in[8];
  const float* ln_mlp_g = (const float*)d_in[9];
  const float* ln_mlp_b = (const float*)d_in[10];
  const float* w2       = (const float*)d_in[11];
  const float* b2       = (const float*)d_in[12];
  const float* ln1_g    = (const float*)d_in[13];
  const float* ln1_b    = (const float*)d_in[14];
  const float* ln2_g    = (const float*)d_in[15];
  const float* ln2_b    = (const float*)d_in[16];
  float* out = (float*)d_out;

  void* p;
  cudaGetSymbolAddress(&p, g_h);  float* h  = (float*)p;
  cudaGetSymbolAddress(&p, g_q);  float* q  = (float*)p;
  cudaGetSymbolAddress(&p, g_k);  float* k  = (float*)p;
  cudaGetSymbolAddress(&p, g_v);  float* v  = (float*)p;
  cudaGetSymbolAddress(&p, g_h2); float* h2 = (float*)p;
  cudaGetSymbolAddress(&p, g_m);  float* m  = (float*)p;
  cudaGetSymbolAddress(&p, g_ah); __nv_bfloat16* ah = (__nv_bfloat16*)p;
  cudaGetSymbolAddress(&p, g_al); __nv_bfloat16* al = (__nv_bfloat16*)p;
  cudaGetSymbolAddress(&p, g_wh); __nv_bfloat16* wh = (__nv_bfloat16*)p;
  cudaGetSymbolAddress(&p, g_wl); __nv_bfloat16* wl = (__nv_bfloat16*)p;

  // 1. h = LN1(x), split to bf16 hi/lo
  ln_kernel<DD, false, false><<<BN, 256>>>(x, nullptr, ln1_g, ln1_b, h);
  run_split(h, ah, al, BN*DD);

  // 2. QKV projections (tensor cores, bf16x3)
  run_split(wq, wh, wl, DD*DD);
  run_gemm(ah, al, wh, wl, bq, q, BN, DD, DD);
  run_split(wk, wh, wl, DD*DD);
  run_gemm(ah, al, wh, wl, bk, k, BN, DD, DD);
  run_split(wv, wh, wl, DD*DD);
  run_gemm(ah, al, wh, wl, bv, v, BN, DD, DD);

  // 3. Causal attention -> reuse g_h as attention output
  attn_kernel<<<dim3(NN/64, BB*HH), 64>>>(q, k, v, h);

  // 4. h2 = LN2(x + attn)
  ln_kernel<DD, false, true><<<BN, 256>>>(x, h, ln2_g, ln2_b, h2);

  // 5. m = h2 @ w1^T + b1 ; m = relu(LN_mlp(m))
  run_split(h2, ah, al, BN*DD);
  run_split(w1, wh, wl, FF*DD);
  run_gemm(ah, al, wh, wl, b1, m, BN, FF, DD);
  ln_kernel<FF, true, false><<<BN, 256>>>(m, nullptr, ln_mlp_g, ln_mlp_b, m);

  // 6. out = m @ w2^T + b2
  run_split(m, ah, al, BN*FF);
  run_split(w2, wh, wl, DD*FF);
  run_gemm(ah, al, wh, wl, b2, out, BN, DD, FF);
}

// round 4
// speedup vs baseline: 2.9140x; 1.6787x over previous
#include <cuda_runtime.h>
#include <cuda_bf16.h>
#include <math.h>
#include <stdint.h>

// Problem dims
#define BB 2
#define NN 2048
#define DD 1024
#define HH 16
#define EE 64
#define FF 4096
#define BN (BB*NN)   // 4096

// ---------------------------------------------------------------------------
// Scratch (device globals: no allocation allowed)
// ---------------------------------------------------------------------------
__device__ float g_o [BN*DD];                    // attention output (fp32)
__device__ float g_m [(size_t)BN*FF];            // FC1 output (fp32)
__device__ __nv_bfloat16 g_ah[(size_t)BN*FF];    // activation hi split
__device__ __nv_bfloat16 g_al[(size_t)BN*FF];    // activation lo split
__device__ __nv_bfloat16 g_wh[(size_t)FF*DD];    // weight hi split
__device__ __nv_bfloat16 g_wl[(size_t)FF*DD];    // weight lo split
__device__ __nv_bfloat16 g_qkvh[(size_t)BN*3072]; // QKV hi split
__device__ __nv_bfloat16 g_qkvl[(size_t)BN*3072]; // QKV lo split
__device__ float g_bias[3072];

// ---------------------------------------------------------------------------
// Helpers
// ---------------------------------------------------------------------------
__device__ __forceinline__ uint32_t s2u(const void* p) {
  uint32_t a;
  asm("{ .reg .u64 t; cvta.to.shared.u64 t, %1; cvt.u32.u64 %0, t; }" : "=r"(a) : "l"(p));
  return a;
}

#define SWZ(off) ((off) ^ (((off) >> 3) & 0x70))

__device__ __forceinline__ void cp16(uint32_t dst, const void* src) {
  asm volatile("cp.async.cg.shared.global [%0], [%1], 16;"
               :: "r"(dst), "l"(__cvta_generic_to_global(src)) : "memory");
}
__device__ __forceinline__ void cp_commit() {
  asm volatile("cp.async.commit_group;" ::: "memory");
}
template<int N>
__device__ __forceinline__ void cp_wait() {
  asm volatile("cp.async.wait_group %0;" :: "n"(N) : "memory");
}

__device__ __forceinline__ void ldsm4(uint32_t* r, uint32_t addr) {
  asm volatile("ldmatrix.sync.aligned.m8n8.x4.shared.b16 {%0,%1,%2,%3}, [%4];"
               : "=r"(r[0]), "=r"(r[1]), "=r"(r[2]), "=r"(r[3]) : "r"(addr));
}
__device__ __forceinline__ void ldsm4t(uint32_t* r, uint32_t addr) {
  asm volatile("ldmatrix.sync.aligned.m8n8.x4.trans.shared.b16 {%0,%1,%2,%3}, [%4];"
               : "=r"(r[0]), "=r"(r[1]), "=r"(r[2]), "=r"(r[3]) : "r"(addr));
}

__device__ __forceinline__ void mma16816(float* c, const uint32_t* a, uint32_t b0, uint32_t b1) {
  asm volatile(
    "mma.sync.aligned.m16n8k16.row.col.f32.bf16.bf16.f32 "
    "{%0,%1,%2,%3}, {%4,%5,%6,%7}, {%8,%9}, {%0,%1,%2,%3};"
    : "+f"(c[0]), "+f"(c[1]), "+f"(c[2]), "+f"(c[3])
    : "r"(a[0]), "r"(a[1]), "r"(a[2]), "r"(a[3]), "r"(b0), "r"(b1));
}

__device__ __forceinline__ float ex2(float x) {
  float r;
  asm("ex2.approx.ftz.f32 %0, %1;" : "=f"(r) : "f"(x));
  return r;
}

__device__ __forceinline__ void pack_split(float x, float y, uint32_t& hi, uint32_t& lo) {
  __nv_bfloat162 h2 = __floats2bfloat162_rn(x, y);
  hi = *(uint32_t*)&h2;
  float rx = x - __bfloat162float(h2.x);
  float ry = y - __bfloat162float(h2.y);
  __nv_bfloat162 l2 = __floats2bfloat162_rn(rx, ry);
  lo = *(uint32_t*)&l2;
}

// ---------------------------------------------------------------------------
// fp32 -> bf16 hi/lo split (for weights)
// ---------------------------------------------------------------------------
__global__ void split_kernel(const float* __restrict__ src,
                             __nv_bfloat16* __restrict__ hi,
                             __nv_bfloat16* __restrict__ lo, int n4) {
  int i = blockIdx.x * blockDim.x + threadIdx.x;
  if (i >= n4) return;
  float4 v = ((const float4*)src)[i];
  uint32_t h0, l0, h1, l1;
  pack_split(v.x, v.y, h0, l0);
  pack_split(v.z, v.w, h1, l1);
  ((uint32_t*)hi)[2*i+0] = h0; ((uint32_t*)hi)[2*i+1] = h1;
  ((uint32_t*)lo)[2*i+0] = l0; ((uint32_t*)lo)[2*i+1] = l1;
}

__global__ void pack_bias(const float* __restrict__ bq, const float* __restrict__ bk,
                          const float* __restrict__ bv, float* __restrict__ dst) {
  int i = blockIdx.x * blockDim.x + threadIdx.x;
  if (i < 1024) { dst[i] = bq[i]; dst[1024+i] = bk[i]; dst[2048+i] = bv[i]; }
}

// ---------------------------------------------------------------------------
// bf16x3 warp-MMA GEMM: C = (Ah+Al)[M,K] @ (Wh+Wl)[Ncols,K]^T + bias
// Output: fp32 C, or bf16 hi/lo split (if Cl != nullptr).
// ---------------------------------------------------------------------------
#define STAGE_BYTES 65536
#define OPB 16384
#define GEMM_SMEM (2 * STAGE_BYTES)

__global__ void __launch_bounds__(256) gemm_mma(
    const __nv_bfloat16* __restrict__ Ah, const __nv_bfloat16* __restrict__ Al,
    const __nv_bfloat16* __restrict__ Wh, const __nv_bfloat16* __restrict__ Wl,
    const float* __restrict__ bias, float* __restrict__ C,
    __nv_bfloat16* __restrict__ Ch, __nv_bfloat16* __restrict__ Cl,
    int M, int Ncols, int K)
{
  extern __shared__ char smem[];
  const uint32_t smem_u = s2u(smem);
  const int tid  = threadIdx.x;
  const int wid  = tid >> 5;
  const int lane = tid & 31;
  const int warp_m = wid & 3;
  const int warp_n = wid >> 2;
  const int bm = blockIdx.y * 128;
  const int bn = blockIdx.x * 128;
  const int T = K >> 6;

  const __nv_bfloat16* srcs[4];
  srcs[0] = Ah + (size_t)bm * K;
  srcs[1] = Al + (size_t)bm * K;
  srcs[2] = Wh + (size_t)bn * K;
  srcs[3] = Wl + (size_t)bn * K;

  int lrow[4], lcol[4];
  #pragma unroll
  for (int i = 0; i < 4; i++) {
    int chunk = i * 256 + tid;
    lrow[i] = chunk >> 3;
    lcol[i] = chunk & 7;
  }

  auto load_stage = [&](int t) {
    const uint32_t sb = smem_u + (uint32_t)(t & 1) * STAGE_BYTES;
    const int k0 = t << 6;
    #pragma unroll
    for (int op = 0; op < 4; op++) {
      const __nv_bfloat16* s = srcs[op] + k0;
      #pragma unroll
      for (int i = 0; i < 4; i++) {
        const uint32_t dst = sb + op * OPB + SWZ(lrow[i] * 128 + lcol[i] * 16);
        cp16(dst, s + (size_t)lrow[i] * K + lcol[i] * 8);
      }
    }
    cp_commit();
  };

  float acc[2][8][4];
  #pragma unroll
  for (int mt = 0; mt < 2; mt++)
    #pragma unroll
    for (int nt = 0; nt < 8; nt++)
      #pragma unroll
      for (int j = 0; j < 4; j++) acc[mt][nt][j] = 0.f;

  load_stage(0);

  const int arow = warp_m * 32 + (lane & 15);
  const int brow = warp_n * 64 + (lane & 15);
  const int kchunk = (lane >> 4) * 16;

  for (int t = 0; t < T; t++) {
    if (t + 1 < T) { load_stage(t + 1); cp_wait<1>(); }
    else          { cp_wait<0>(); }
    __syncthreads();

    const uint32_t sb  = smem_u + (uint32_t)(t & 1) * STAGE_BYTES;
    const uint32_t sAh = sb, sAl = sb + OPB, sWh = sb + 2*OPB, sWl = sb + 3*OPB;

    #pragma unroll
    for (int ks = 0; ks < 4; ks++) {
      const int koff = ks * 32 + kchunk;
      uint32_t ah[2][4], al[2][4], wh[4][4], wl[4][4];
      #pragma unroll
      for (int mt = 0; mt < 2; mt++) {
        const uint32_t off = SWZ((arow + mt*16) * 128 + koff);
        ldsm4(ah[mt], sAh + off);
        ldsm4(al[mt], sAl + off);
      }
      #pragma unroll
      for (int ng = 0; ng < 4; ng++) {
        const uint32_t off = SWZ((brow + ng*16) * 128 + koff);
        ldsm4(wh[ng], sWh + off);
        ldsm4(wl[ng], sWl + off);
      }
      #pragma unroll
      for (int mt = 0; mt < 2; mt++) {
        #pragma unroll
        for (int nt = 0; nt < 8; nt++) {
          const int ng = nt >> 1, half = nt & 1;
          mma16816(acc[mt][nt], ah[mt], wh[ng][half], wh[ng][half+2]);
          mma16816(acc[mt][nt], ah[mt], wl[ng][half], wl[ng][half+2]);
          mma16816(acc[mt][nt], al[mt], wh[ng][half], wh[ng][half+2]);
        }
      }
    }
    __syncthreads();
  }

  const int g  = lane >> 2;
  const int tg = lane & 3;
  const bool split = (Cl != nullptr);
  #pragma unroll
  for (int mt = 0; mt < 2; mt++) {
    const int r0 = bm + warp_m*32 + mt*16 + g;
    #pragma unroll
    for (int nt = 0; nt < 8; nt++) {
      const int col = bn + warp_n*64 + nt*8 + tg*2;
      const float b0 = bias[col], b1 = bias[col+1];
      const float v00 = acc[mt][nt][0] + b0, v01 = acc[mt][nt][1] + b1;
      const float v10 = acc[mt][nt][2] + b0, v11 = acc[mt][nt][3] + b1;
      if (split) {
        uint32_t h0, l0, h1, l1;
        pack_split(v00, v01, h0, l0);
        pack_split(v10, v11, h1, l1);
        *(uint32_t*)(Ch + (size_t)r0 * Ncols + col)     = h0;
        *(uint32_t*)(Cl + (size_t)r0 * Ncols + col)     = l0;
        *(uint32_t*)(Ch + (size_t)(r0+8) * Ncols + col) = h1;
        *(uint32_t*)(Cl + (size_t)(r0+8) * Ncols + col) = l1;
      } else {
        *(float2*)(C + (size_t)r0 * Ncols + col)     = make_float2(v00, v01);
        *(float2*)(C + (size_t)(r0+8) * Ncols + col) = make_float2(v10, v11);
      }
    }
  }
}

// ---------------------------------------------------------------------------
// Block-wide 2-value sum reduction (256 threads)
// ---------------------------------------------------------------------------
__device__ __forceinline__ void block_reduce2(float& a, float& b) {
  #pragma unroll
  for (int o = 16; o > 0; o >>= 1) {
    a += __shfl_xor_sync(0xffffffffu, a, o);
    b += __shfl_xor_sync(0xffffffffu, b, o);
  }
  __shared__ float sa[8], sb[8];
  int w = threadIdx.x >> 5, l = threadIdx.x & 31;
  if (l == 0) { sa[w] = a; sb[w] = b; }
  __syncthreads();
  float ra = (l < 8) ? sa[l] : 0.f;
  float rb = (l < 8) ? sb[l] : 0.f;
  #pragma unroll
  for (int o = 4; o > 0; o >>= 1) {
    ra += __shfl_xor_sync(0xffffffffu, ra, o);
    rb += __shfl_xor_sync(0xffffffffu, rb, o);
  }
  if (threadIdx.x == 0) { sa[0] = ra; sb[0] = rb; }
  __syncthreads();
  a = sa[0]; b = sb[0];
}

// ---------------------------------------------------------------------------
// LayerNorm: dst = LN(src (+add))*g + b, optional ReLU, optional bf16-split out
// ---------------------------------------------------------------------------
template<int COLS, bool RELU, bool ADD, bool SPLIT>
__global__ void ln_kernel(const float* __restrict__ src,
                          const float* __restrict__ addsrc,
                          const float* __restrict__ gw,
                          const float* __restrict__ bw,
                          float* __restrict__ dst,
                          __nv_bfloat16* __restrict__ dsth,
                          __nv_bfloat16* __restrict__ dstl)
{
  __shared__ float row[COLS];
  const size_t r = blockIdx.x;
  const float4* s4 = (const float4*)(src + r * COLS);
  const float4* a4 = ADD ? (const float4*)(addsrc + r * COLS) : nullptr;

  float sum = 0.f, sq = 0.f;
  #pragma unroll
  for (int i = threadIdx.x; i < COLS/4; i += 256) {
    float4 v = s4[i];
    if (ADD) {
      float4 a = a4[i];
      v.x += a.x; v.y += a.y; v.z += a.z; v.w += a.w;
    }
    ((float4*)row)[i] = v;
    sum += v.x + v.y + v.z + v.w;
    sq  += v.x*v.x + v.y*v.y + v.z*v.z + v.w*v.w;
  }
  block_reduce2(sum, sq);
  const float mu  = sum * (1.0f / COLS);
  const float var = sq * (1.0f / COLS) - mu * mu;
  const float inv = rsqrtf(var + 1e-5f);

  #pragma unroll
  for (int i = threadIdx.x; i < COLS/4; i += 256) {
    float4 v = ((float4*)row)[i];
    float4 g = ((const float4*)gw)[i];
    float4 b = ((const float4*)bw)[i];
    float4 o;
    o.x = (v.x - mu) * inv * g.x + b.x;
    o.y = (v.y - mu) * inv * g.y + b.y;
    o.z = (v.z - mu) * inv * g.z + b.z;
    o.w = (v.w - mu) * inv * g.w + b.w;
    if (RELU) {
      o.x = fmaxf(o.x, 0.f); o.y = fmaxf(o.y, 0.f);
      o.z = fmaxf(o.z, 0.f); o.w = fmaxf(o.w, 0.f);
    }
    if (SPLIT) {
      uint32_t h0, l0, h1, l1;
      pack_split(o.x, o.y, h0, l0);
      pack_split(o.z, o.w, h1, l1);
      ((uint32_t*)(dsth + r * COLS))[2*i+0] = h0;
      ((uint32_t*)(dsth + r * COLS))[2*i+1] = h1;
      ((uint32_t*)(dstl + r * COLS))[2*i+0] = l0;
      ((uint32_t*)(dstl + r * COLS))[2*i+1] = l1;
    } else {
      ((float4*)(dst + r * COLS))[i] = o;
    }
  }
}

// ---------------------------------------------------------------------------
// MMA flash attention (causal), bf16x3 splits for QK^T and PV.
// Q tile 128 rows/block, K/V tiles of 64 keys, 8 warps x 16 rows.
// QKV packed layout: [BN][3072], Q at col h*64, K at 1024+h*64, V at 2048+h*64.
// ---------------------------------------------------------------------------
#define ATTN_SMEM 98304
#define CSC 46.166241308446828f   // 32 * log2(e)

__global__ void __launch_bounds__(256) attn_mma(
    const __nv_bfloat16* __restrict__ QKVh,
    const __nv_bfloat16* __restrict__ QKVl,
    float* __restrict__ O)
{
  extern __shared__ char smem[];
  const uint32_t su = s2u(smem);
  const uint32_t sQh = su, sQl = su + 16384;
  const int tid = threadIdx.x, lane = tid & 31, wid = tid >> 5;
  const int qt = 15 - (int)blockIdx.x;      // heavy tiles first
  const int bh = blockIdx.y, b = bh >> 4, h = bh & 15;
  const size_t rowbase = (size_t)b * NN * 3072;
  const __nv_bfloat16* Qhp = QKVh + rowbase + h*64;
  const __nv_bfloat16* Qlp = QKVl + rowbase + h*64;
  const __nv_bfloat16* Khp = QKVh + rowbase + 1024 + h*64;
  const __nv_bfloat16* Klp = QKVl + rowbase + 1024 + h*64;
  const __nv_bfloat16* Vhp = QKVh + rowbase + 2048 + h*64;
  const __nv_bfloat16* Vlp = QKVl + rowbase + 2048 + h*64;
  const int ktmax = 2*qt + 1;

  // Q tile: 128 rows x 64 cols (128B rows, SW128)
  #pragma unroll
  for (int i = 0; i < 4; i++) {
    int ch = i*256 + tid; int r = ch >> 3, c = ch & 7;
    const size_t go = (size_t)(qt*128 + r) * 3072 + c*8;
    uint32_t d = SWZ(r*128 + c*16);
    cp16(sQh + d, Qhp + go);
    cp16(sQl + d, Qlp + go);
  }
  auto load_kv = [&](int kt) {
    const uint32_t sb = su + 32768 + (uint32_t)(kt & 1) * 32768;
    #pragma unroll
    for (int i = 0; i < 2; i++) {
      int ch = i*256 + tid; int r = ch >> 3, c = ch & 7;
      const size_t go = (size_t)(kt*64 + r) * 3072 + c*8;
      uint32_t d = SWZ(r*128 + c*16);
      cp16(sb + d,         Khp + go);
      cp16(sb + 8192 + d,  Klp + go);
      cp16(sb + 16384 + d, Vhp + go);
      cp16(sb + 24576 + d, Vlp + go);
    }
  };
  load_kv(0);
  cp_commit();

  const int qrow0 = qt*128 + wid*16;
  const int g = lane >> 2, tg = lane & 3;
  uint32_t qh[4][4], ql[4][4];
  float o[8][4];
  #pragma unroll
  for (int nt = 0; nt < 8; nt++)
    #pragma unroll
    for (int j = 0; j < 4; j++) o[nt][j] = 0.f;
  float m0 = -1e30f, m1 = -1e30f, l0 = 0.f, l1 = 0.f;

  for (int kt = 0; kt <= ktmax; kt++) {
    if (kt < ktmax) { load_kv(kt+1); cp_commit(); cp_wait<1>(); }
    else            { cp_wait<0>(); }
    __syncthreads();

    if (kt == 0) {
      #pragma unroll
      for (int ks = 0; ks < 4; ks++) {
        uint32_t off = SWZ((wid*16 + (lane & 15)) * 128 + ks*32 + (lane >> 4)*16);
        ldsm4(qh[ks], sQh + off);
        ldsm4(ql[ks], sQl + off);
      }
    }

    const bool active = (kt*64) <= (qrow0 + 15);
    if (active) {
      const uint32_t sb = su + 32768 + (uint32_t)(kt & 1) * 32768;
      const uint32_t sKh_ = sb, sKl_ = sb + 8192, sVh_ = sb + 16384, sVl_ = sb + 24576;

      // S = Q @ K^T (bf16x3)
      float s[8][4];
      #pragma unroll
      for (int nt = 0; nt < 8; nt++)
        #pragma unroll
        for (int j = 0; j < 4; j++) s[nt][j] = 0.f;
      #pragma unroll
      for (int ks = 0; ks < 4; ks++) {
        uint32_t kh[4][4], kl[4][4];
        #pragma unroll
        for (int ng = 0; ng < 4; ng++) {
          uint32_t off = SWZ((ng*16 + (lane & 15)) * 128 + ks*32 + (lane >> 4)*16);
          ldsm4(kh[ng], sKh_ + off);
          ldsm4(kl[ng], sKl_ + off);
        }
        #pragma unroll
        for (int nt = 0; nt < 8; nt++) {
          const int ng = nt >> 1, hf = nt & 1;
          mma16816(s[nt], qh[ks], kh[ng][hf], kh[ng][hf+2]);
          mma16816(s[nt], qh[ks], kl[ng][hf], kl[ng][hf+2]);
          mma16816(s[nt], ql[ks], kh[ng][hf], kh[ng][hf+2]);
        }
      }

      // scale to log2 domain + causal mask
      const bool needmask = (kt*64 + 63) > qrow0;
      #pragma unroll
      for (int nt = 0; nt < 8; nt++) {
        #pragma unroll
        for (int j = 0; j < 4; j++) {
          float v = s[nt][j] * CSC;
          if (needmask) {
            const int key = kt*64 + nt*8 + 2*tg + (j & 1);
            const int rw  = qrow0 + g + 8*(j >> 1);
            if (key > rw) v = -1e30f;
          }
          s[nt][j] = v;
        }
      }

      // row max (rows g and g+8)
      float ml0 = -1e30f, ml1 = -1e30f;
      #pragma unroll
      for (int nt = 0; nt < 8; nt++) {
        ml0 = fmaxf(ml0, fmaxf(s[nt][0], s[nt][1]));
        ml1 = fmaxf(ml1, fmaxf(s[nt][2], s[nt][3]));
      }
      #pragma unroll
      for (int off = 1; off <= 2; off <<= 1) {
        ml0 = fmaxf(ml0, __shfl_xor_sync(0xffffffffu, ml0, off));
        ml1 = fmaxf(ml1, __shfl_xor_sync(0xffffffffu, ml1, off));
      }
      const float mn0 = fmaxf(m0, ml0);
      const float mn1 = fmaxf(m1, ml1);
      const float f0 = ex2(m0 - mn0);
      const float f1 = ex2(m1 - mn1);
      m0 = mn0; m1 = mn1;

      // P = exp2(S - m), l update, O rescale
      float ps0 = 0.f, ps1 = 0.f;
      #pragma unroll
      for (int nt = 0; nt < 8; nt++) {
        s[nt][0] = ex2(s[nt][0] - mn0);
        s[nt][1] = ex2(s[nt][1] - mn0);
        s[nt][2] = ex2(s[nt][2] - mn1);
        s[nt][3] = ex2(s[nt][3] - mn1);
        ps0 += s[nt][0] + s[nt][1];
        ps1 += s[nt][2] + s[nt][3];
      }
      l0 = l0 * f0 + ps0;
      l1 = l1 * f1 + ps1;
      #pragma unroll
      for (int nt = 0; nt < 8; nt++) {
        o[nt][0] *= f0; o[nt][1] *= f0;
        o[nt][2] *= f1; o[nt][3] *= f1;
      }

      // pack P -> bf16 hi/lo A-frags
      uint32_t ph0[8], ph1[8], pl0[8], pl1[8];
      #pragma unroll
      for (int nt = 0; nt < 8; nt++) {
        pack_split(s[nt][0], s[nt][1], ph0[nt], pl0[nt]);
        pack_split(s[nt][2], s[nt][3], ph1[nt], pl1[nt]);
      }

      // O += P @ V (bf16x3); V via ldmatrix.trans
      #pragma unroll
      for (int ks = 0; ks < 4; ks++) {
        uint32_t aPh[4] = { ph0[2*ks], ph1[2*ks], ph0[2*ks+1], ph1[2*ks+1] };
        uint32_t aPl[4] = { pl0[2*ks], pl1[2*ks], pl0[2*ks+1], pl1[2*ks+1] };
        uint32_t vh[4][4], vl[4][4];
        const int krow = ks*16 + (lane & 7) + ((lane >> 4) << 3);
        const int nb0  = ((lane >> 3) & 1) * 16;
        #pragma unroll
        for (int ng2 = 0; ng2 < 4; ng2++) {
          uint32_t off = SWZ(krow*128 + ng2*32 + nb0);
          ldsm4t(vh[ng2], sVh_ + off);
          ldsm4t(vl[ng2], sVl_ + off);
        }
        #pragma unroll
        for (int nt = 0; nt < 8; nt++) {
          const int ng2 = nt >> 1, hf = nt & 1;
          mma16816(o[nt], aPh, vh[ng2][hf], vh[ng2][hf+2]);
          mma16816(o[nt], aPh, vl[ng2][hf], vl[ng2][hf+2]);
          mma16816(o[nt], aPl, vh[ng2][hf], vh[ng2][hf+2]);
        }
      }
    }
    __syncthreads();
  }

  // finalize: reduce l over the 4 lanes of each row, scale, store
  l0 += __shfl_xor_sync(0xffffffffu, l0, 1);
  l0 += __shfl_xor_sync(0xffffffffu, l0, 2);
  l1 += __shfl_xor_sync(0xffffffffu, l1, 1);
  l1 += __shfl_xor_sync(0xffffffffu, l1, 2);
  const float i0 = 1.0f / l0;
  const float i1 = 1.0f / l1;
  const size_t orow0 = (size_t)(b*NN + qrow0 + g) * DD + h*64;
  #pragma unroll
  for (int nt = 0; nt < 8; nt++) {
    const int col = nt*8 + tg*2;
    *(float2*)(O + orow0 + col)          = make_float2(o[nt][0]*i0, o[nt][1]*i0);
    *(float2*)(O + orow0 + 8*DD + col)   = make_float2(o[nt][2]*i1, o[nt][3]*i1);
  }
}

// ---------------------------------------------------------------------------
// Launch
// ---------------------------------------------------------------------------
static void run_split(const float* src, __nv_bfloat16* hi, __nv_bfloat16* lo, int n) {
  int n4 = n / 4;
  split_kernel<<<(n4 + 255) / 256, 256>>>(src, hi, lo, n4);
}

static void run_gemm(const __nv_bfloat16* ah, const __nv_bfloat16* al,
                     const __nv_bfloat16* wh, const __nv_bfloat16* wl,
                     const float* bias, float* c, __nv_bfloat16* ch, __nv_bfloat16* cl,
                     int M, int Ncols, int K) {
  cudaFuncSetAttribute(gemm_mma, cudaFuncAttributeMaxDynamicSharedMemorySize, GEMM_SMEM);
  gemm_mma<<<dim3(Ncols/128, M/128), 256, GEMM_SMEM>>>(ah, al, wh, wl, bias, c, ch, cl, M, Ncols, K);
}

extern "C" void kernel_launch(void* const* d_in, const int* in_sizes, int n_in,
                              void* d_out, int out_size)
{
  const float* x        = (const float*)d_in[0];
  const float* wq       = (const float*)d_in[1];
  const float* bq       = (const float*)d_in[2];
  const float* wk       = (const float*)d_in[3];
  const float* bk       = (const float*)d_in[4];
  const float* wv       = (const float*)d_in[5];
  const float* bv       = (const float*)d_in[6];
  const float* w1       = (const float*)d_in[7];
  const float* b1       = (const float*)d_in[8];
  const float* ln_mlp_g = (const float*)d_in[9];
  const float* ln_mlp_b = (const float*)d_in[10];
  const float* w2       = (const float*)d_in[11];
  const float* b2       = (const float*)d_in[12];
  const float* ln1_g    = (const float*)d_in[13];
  const float* ln1_b    = (const float*)d_in[14];
  const float* ln2_g    = (const float*)d_in[15];
  const float* ln2_b    = (const float*)d_in[16];
  float* out = (float*)d_out;

  void* p;
  cudaGetSymbolAddress(&p, g_o);    float* o  = (float*)p;
  cudaGetSymbolAddress(&p, g_m);    float* m  = (float*)p;
  cudaGetSymbolAddress(&p, g_ah);   __nv_bfloat16* ah = (__nv_bfloat16*)p;
  cudaGetSymbolAddress(&p, g_al);   __nv_bfloat16* al = (__nv_bfloat16*)p;
  cudaGetSymbolAddress(&p, g_wh);   __nv_bfloat16* wh = (__nv_bfloat16*)p;
  cudaGetSymbolAddress(&p, g_wl);   __nv_bfloat16* wl = (__nv_bfloat16*)p;
  cudaGetSymbolAddress(&p, g_qkvh); __nv_bfloat16* qkvh = (__nv_bfloat16*)p;
  cudaGetSymbolAddress(&p, g_qkvl); __nv_bfloat16* qkvl = (__nv_bfloat16*)p;
  cudaGetSymbolAddress(&p, g_bias); float* bias3 = (float*)p;

  // 1. LN1(x) -> bf16 splits
  ln_kernel<DD, false, false, true><<<BN, 256>>>(x, nullptr, ln1_g, ln1_b, nullptr, ah, al);

  // 2. packed QKV weights/bias splits + one fused QKV GEMM -> split output
  run_split(wq, wh, wl, DD*DD);
  run_split(wk, wh + DD*DD, wl + DD*DD, DD*DD);
  run_split(wv, wh + 2*DD*DD, wl + 2*DD*DD, DD*DD);
  pack_bias<<<4, 256>>>(bq, bk, bv, bias3);
  run_gemm(ah, al, wh, wl, bias3, nullptr, qkvh, qkvl, BN, 3072, DD);

  // 3. MMA flash attention
  cudaFuncSetAttribute(attn_mma, cudaFuncAttributeMaxDynamicSharedMemorySize, ATTN_SMEM);
  attn_mma<<<dim3(16, BB*HH), 256, ATTN_SMEM>>>(qkvh, qkvl, o);

  // 4. LN2(x + attn) -> splits
  ln_kernel<DD, false, true, true><<<BN, 256>>>(x, o, ln2_g, ln2_b, nullptr, ah, al);

  // 5. FC1 -> m (fp32), then relu(LN_mlp(m)) -> splits
  run_split(w1, wh, wl, FF*DD);
  run_gemm(ah, al, wh, wl, b1, m, nullptr, nullptr, BN, FF, DD);
  ln_kernel<FF, true, false, true><<<BN, 256>>>(m, nullptr, ln_mlp_g, ln_mlp_b, nullptr, ah, al);

  // 6. FC2 -> out
  run_split(w2, wh, wl, DD*FF);
  run_gemm(ah, al, wh, wl, b2, out, nullptr, nullptr, BN, DD, FF);
}